// round 9
// baseline (speedup 1.0000x reference)
#include <cuda_runtime.h>
#include <cuda_bf16.h>
#include <cstdint>
#include <math.h>

typedef __nv_bfloat16 bf16;

#define B_ROWS   512
#define T_STEPS  128
#define DIM_IN   256
#define HDIM     1024
#define FOURH    4096

#define BM 64
#define BN 64            // columns per gate per block
#define NTH 256          // 8 warps: 2 (m, 32 rows) x 4 (n, 16 cols)

// Tile images (gmem layout == smem layout):
// A tile: [2 planes][64 rows][80 B]  = 10240 B
// B tile: [2 planes][256 rows][80 B] = 40960 B  (row = gate*64 + n_local)
#define A_TILE_B  10240
#define B_TILE_B  40960
#define A_PLANE_B 5120
#define B_PLANE_B 20480
#define STAGE_B   (A_TILE_B + B_TILE_B)          // 51200

// smem: [0..24) 3 mbarriers, stages at 1024
#define SM_A_OFF(s) (1024 + (s) * STAGE_B)
#define SM_B_OFF(s) (SM_A_OFF(s) + A_TILE_B)
#define SMEM_BYTES  (1024 + 3 * STAGE_B)         // 154624

// ---------------- persistent device scratch (sorted row space) ----------------
__device__ __align__(128) char g_xt[(size_t)T_STEPS * 8 * 8 * A_TILE_B];
__device__ __align__(128) char g_h1t[2][(size_t)8 * 32 * A_TILE_B];
__device__ __align__(128) char g_h2t[2][(size_t)8 * 32 * A_TILE_B];
__device__ __align__(128) char g_w1t[(size_t)16 * 8  * B_TILE_B];
__device__ __align__(128) char g_u1t[(size_t)16 * 32 * B_TILE_B];
__device__ __align__(128) char g_w2t[(size_t)16 * 32 * B_TILE_B];
__device__ __align__(128) char g_u2t[(size_t)16 * 32 * B_TILE_B];
__device__ float g_c1[(size_t)B_ROWS * HDIM];
__device__ float g_c2[(size_t)B_ROWS * HDIM];
__device__ float g_hfinal[(size_t)B_ROWS * HDIM];
__device__ int   g_perm[B_ROWS];
__device__ int   g_slen[B_ROWS];
__device__ int   g_nact[T_STEPS];

// ---------------- helpers ----------------
__device__ __forceinline__ uint32_t smem_u32(const void* p) {
    uint32_t a;
    asm("{ .reg .u64 t; cvta.to.shared.u64 t, %1; cvt.u32.u64 %0, t; }" : "=r"(a) : "l"(p));
    return a;
}
__device__ __forceinline__ void mbar_init(uint32_t a, uint32_t cnt) {
    asm volatile("mbarrier.init.shared.b64 [%0], %1;" :: "r"(a), "r"(cnt) : "memory");
}
__device__ __forceinline__ void mbar_expect(uint32_t a, uint32_t bytes) {
    asm volatile("mbarrier.arrive.expect_tx.shared.b64 _, [%0], %1;"
                 :: "r"(a), "r"(bytes) : "memory");
}
__device__ __forceinline__ void mbar_wait(uint32_t a, uint32_t parity) {
    asm volatile(
        "{\n\t.reg .pred P;\n\t"
        "WL_%=:\n\t"
        "mbarrier.try_wait.parity.acquire.cta.shared::cta.b64 P, [%0], %1, 0x989680;\n\t"
        "@P bra.uni WD_%=;\n\t"
        "bra.uni WL_%=;\n\t"
        "WD_%=:\n\t}"
        :: "r"(a), "r"(parity) : "memory");
}
__device__ __forceinline__ void bulk_g2s(uint32_t dst, const void* src,
                                         uint32_t bytes, uint32_t mbar) {
    asm volatile(
        "cp.async.bulk.shared::cluster.global.mbarrier::complete_tx::bytes "
        "[%0], [%1], %2, [%3];"
        :: "r"(dst), "l"(src), "r"(bytes), "r"(mbar) : "memory");
}
__device__ __forceinline__ void ldmx4(uint32_t* r, uint32_t a) {
    asm volatile("ldmatrix.sync.aligned.m8n8.x4.shared.b16 {%0,%1,%2,%3}, [%4];"
                 : "=r"(r[0]), "=r"(r[1]), "=r"(r[2]), "=r"(r[3]) : "r"(a));
}
__device__ __forceinline__ void ldmx2(uint32_t* r, uint32_t a) {
    asm volatile("ldmatrix.sync.aligned.m8n8.x2.shared.b16 {%0,%1}, [%2];"
                 : "=r"(r[0]), "=r"(r[1]) : "r"(a));
}
__device__ __forceinline__ void mma_bf16(float* d, const uint32_t* a, const uint32_t* b) {
    asm volatile(
        "mma.sync.aligned.m16n8k16.row.col.f32.bf16.bf16.f32 "
        "{%0,%1,%2,%3}, {%4,%5,%6,%7}, {%8,%9}, {%0,%1,%2,%3};"
        : "+f"(d[0]), "+f"(d[1]), "+f"(d[2]), "+f"(d[3])
        : "r"(a[0]), "r"(a[1]), "r"(a[2]), "r"(a[3]), "r"(b[0]), "r"(b[1]));
}
__device__ __forceinline__ float fsig(float x) { return 1.0f / (1.0f + __expf(-x)); }
__device__ __forceinline__ void split_bf16(float x, bf16& hi, bf16& lo) {
    hi = __float2bfloat16(x);
    lo = __float2bfloat16(x - __bfloat162float(hi));
}

// ---------------- prep kernels ----------------
__global__ void sort_rows(const int* __restrict__ seqlen,
                          int* __restrict__ perm, int* __restrict__ slen,
                          int* __restrict__ nact) {
    __shared__ int keys[B_ROWS];
    const int i = threadIdx.x;
    keys[i] = seqlen[i];
    __syncthreads();
    const int k = keys[i];
    int rank = 0;
    for (int j = 0; j < B_ROWS; ++j) {
        int kj = keys[j];
        rank += (kj > k) || (kj == k && j < i);
    }
    perm[rank] = i;
    slen[rank] = k;
    if (i < T_STEPS) {
        int cnt = 0;
        for (int j = 0; j < B_ROWS; ++j) cnt += (keys[j] >= i + 1);
        nact[i] = cnt;
    }
}

__global__ void split_chars_tiled(const float* __restrict__ x,
                                  const int* __restrict__ perm,
                                  char* __restrict__ xt) {
    const int n = B_ROWS * T_STEPS * DIM_IN;
    int i = blockIdx.x * blockDim.x + threadIdx.x;
    if (i >= n) return;
    const int row_elems = T_STEPS * DIM_IN;
    int bs = i / row_elems, d = i - bs * row_elems;
    int t = d >> 8, k = d & 255;
    float v = x[(size_t)perm[bs] * row_elems + d];
    bf16 h, l; split_bf16(v, h, l);
    size_t base = (((size_t)t * 8 + (bs >> 6)) * 8 + (k >> 5)) * A_TILE_B
                + (size_t)(bs & 63) * 80 + (k & 31) * 2;
    *reinterpret_cast<bf16*>(xt + base)             = h;
    *reinterpret_cast<bf16*>(xt + base + A_PLANE_B) = l;
}

// All four weight transposes in ONE launch (z selects the matrix) so that the
// lstm_step launches start at index 3 and ncu (-s 5) captures lstm_step.
struct TransArgs { const float* W; char* Wt; int K; };
__global__ void transpose_split_w_all(TransArgs t0, TransArgs t1,
                                      TransArgs t2, TransArgs t3) {
    TransArgs ta = (blockIdx.z == 0) ? t0
                 : (blockIdx.z == 1) ? t1
                 : (blockIdx.z == 2) ? t2 : t3;
    int kb = blockIdx.y * 32;
    if (kb >= ta.K) return;
    __shared__ float tile[32][33];
    int nb = blockIdx.x * 32;
    int x = threadIdx.x, y = threadIdx.y;
    #pragma unroll
    for (int yy = y; yy < 32; yy += 8)
        tile[yy][x] = ta.W[(size_t)(kb + yy) * FOURH + nb + x];
    __syncthreads();
    const int KC = ta.K >> 5;
    #pragma unroll
    for (int yy = y; yy < 32; yy += 8) {
        float w = tile[x][yy];
        bf16 h, l; split_bf16(w, h, l);
        int n4 = nb + yy, k = kb + x;
        int g = n4 >> 10, rr = n4 & 1023;
        int nblk = rr >> 6, nl = rr & 63;
        int kc = k >> 5, kl = k & 31;
        size_t base = ((size_t)(nblk * KC + kc)) * B_TILE_B
                    + (size_t)(g * 64 + nl) * 80 + kl * 2;
        *reinterpret_cast<bf16*>(ta.Wt + base)             = h;
        *reinterpret_cast<bf16*>(ta.Wt + base + B_PLANE_B) = l;
    }
}

// ---------------- per-layer step arguments ----------------
struct StepArgs {
    const char* Ax;      // tiled X (A seg0), layout [rowblk][KC0]
    const char* Hx;      // tiled Hprev (A seg1), layout [rowblk][32]
    const char* Bw;      // tiled W (B seg0), layout [nblk][KC0]
    const char* Bu;      // tiled U (B seg1), layout [nblk][32]
    int KC0;
    const float* bias;
    float* C;
    char* Ot;            // tiled h output, layout [rowblk][32]
    const int* seqlen;
    float* hfinal;
    const int* nact;
    int t; int first;
};

// ---------------- fused dual-layer LSTM step (bf16x3, 8 warps, 2 m-tiles) --------
__global__ __launch_bounds__(NTH)
void lstm_step(const StepArgs a0, const StepArgs a1)
{
    const StepArgs a = (blockIdx.z == 0) ? a0 : a1;
    const int rowblk = blockIdx.y;
    const int row0 = rowblk * BM;
    if (row0 >= a.nact[a.t]) return;

    extern __shared__ char smemc[];
    const uint32_t sb = smem_u32(smemc);
    const int tid  = threadIdx.x;
    const int lane = tid & 31;
    const int warp = tid >> 5;
    const int wm   = warp >> 2;          // 0..1 -> 32-row slab
    const int wn   = warp & 3;           // 0..3 -> 16-col slab
    const int nblk = blockIdx.x;
    const int n0   = nblk * BN;

    const int arow  = (lane & 7) + ((lane >> 3) & 1) * 8;
    const int koffA = (lane >> 4) * 8;
    const int laneb = lane & 15;
    const int brow  = laneb & 7;
    const int koffB = ((laneb >> 3) & 1) * 8;

    float acc[4][2][2][4];               // [gate][mt][nt][frag]
    #pragma unroll
    for (int g = 0; g < 4; ++g)
        #pragma unroll
        for (int mt = 0; mt < 2; ++mt)
            #pragma unroll
            for (int nt = 0; nt < 2; ++nt)
                #pragma unroll
                for (int q = 0; q < 4; ++q) acc[g][mt][nt][q] = 0.f;

    const int KC0i = a.KC0;
    const int nch = a.first ? KC0i : (KC0i + 32);

    auto issue = [&](int c) {
        const int st = c % 3;
        const uint32_t mb = sb + st * 8;
        const int seg = (c < KC0i) ? 0 : 1;
        const int kc  = seg ? (c - KC0i) : c;
        const char* As = seg ? (a.Hx + ((size_t)(rowblk * 32 + kc)) * A_TILE_B)
                             : (a.Ax + ((size_t)(rowblk * KC0i + kc)) * A_TILE_B);
        const char* Bs = seg ? (a.Bu + ((size_t)(nblk * 32 + kc)) * B_TILE_B)
                             : (a.Bw + ((size_t)(nblk * KC0i + kc)) * B_TILE_B);
        mbar_expect(mb, STAGE_B);
        bulk_g2s(sb + SM_A_OFF(st), As, A_TILE_B, mb);
        bulk_g2s(sb + SM_B_OFF(st), Bs, B_TILE_B, mb);
    };

    if (tid == 0) {
        #pragma unroll
        for (int s = 0; s < 3; ++s) mbar_init(sb + s * 8, 1);
        asm volatile("fence.proxy.async.shared::cta;" ::: "memory");
        issue(0);
        if (nch > 1) issue(1);
    }
    __syncthreads();

    for (int i = 0; i < nch; ++i) {
        mbar_wait(sb + (i % 3) * 8, (uint32_t)((i / 3) & 1));
        __syncthreads();
        if (tid == 0 && i + 2 < nch) issue(i + 2);

        const int st = i % 3;
        const uint32_t aB = sb + SM_A_OFF(st);
        const uint32_t bB = sb + SM_B_OFF(st);

        #pragma unroll
        for (int ks = 0; ks < 2; ++ks) {
            uint32_t ah[2][4], al[2][4];
            #pragma unroll
            for (int mt = 0; mt < 2; ++mt) {
                uint32_t aa = aB + (uint32_t)((wm * 32 + mt * 16 + arow) * 80
                                              + (ks * 16 + koffA) * 2);
                ldmx4(ah[mt], aa);
                ldmx4(al[mt], aa + A_PLANE_B);
            }
            #pragma unroll
            for (int g = 0; g < 4; ++g) {
                #pragma unroll
                for (int nt = 0; nt < 2; ++nt) {
                    uint32_t ba = bB + (uint32_t)((g * 64 + wn * 16 + nt * 8 + brow) * 80
                                                  + (ks * 16 + koffB) * 2);
                    uint32_t bh[2], bl[2];
                    ldmx2(bh, ba);
                    ldmx2(bl, ba + B_PLANE_B);
                    #pragma unroll
                    for (int mt = 0; mt < 2; ++mt) {
                        mma_bf16(acc[g][mt][nt], ah[mt], bh);
                        mma_bf16(acc[g][mt][nt], ah[mt], bl);
                        mma_bf16(acc[g][mt][nt], al[mt], bh);
                    }
                }
            }
        }
    }

    // ---- fused LSTM cell epilogue (h written in tiled A-image layout) ----
    #pragma unroll
    for (int mt = 0; mt < 2; ++mt) {
        #pragma unroll
        for (int half = 0; half < 2; ++half) {
            const int r = row0 + wm * 32 + mt * 16 + half * 8 + (lane >> 2);
            const int slen = a.seqlen ? a.seqlen[r] : 0;
            #pragma unroll
            for (int nt = 0; nt < 2; ++nt) {
                const int c = n0 + wn * 16 + nt * 8 + (lane & 3) * 2;
                float2 cold = make_float2(0.f, 0.f);
                if (!a.first)
                    cold = *reinterpret_cast<const float2*>(a.C + (size_t)r * HDIM + c);
                float cn[2], hn[2];
                #pragma unroll
                for (int j = 0; j < 2; ++j) {
                    const int q = half * 2 + j;
                    float zi = acc[0][mt][nt][q] + a.bias[c + j];
                    float zf = acc[1][mt][nt][q] + a.bias[HDIM + c + j];
                    float zg = acc[2][mt][nt][q] + a.bias[2 * HDIM + c + j];
                    float zo = acc[3][mt][nt][q] + a.bias[3 * HDIM + c + j];
                    float ig = fsig(zi), fg = fsig(zf);
                    float gg = tanhf(zg), og = fsig(zo);
                    float co = (j == 0) ? cold.x : cold.y;
                    cn[j] = fmaf(fg, co, ig * gg);
                    hn[j] = og * tanhf(cn[j]);
                }
                *reinterpret_cast<float2*>(a.C + (size_t)r * HDIM + c) = make_float2(cn[0], cn[1]);
                bf16 h0, l0, h1, l1;
                split_bf16(hn[0], h0, l0);
                split_bf16(hn[1], h1, l1);
                size_t toff = ((size_t)((r >> 6) * 32 + (c >> 5))) * A_TILE_B
                            + (size_t)(r & 63) * 80 + (c & 31) * 2;
                *reinterpret_cast<__nv_bfloat162*>(a.Ot + toff) = __nv_bfloat162(h0, h1);
                *reinterpret_cast<__nv_bfloat162*>(a.Ot + toff + A_PLANE_B) =
                    __nv_bfloat162(l0, l1);
                if (a.hfinal && slen - 1 == a.t)
                    *reinterpret_cast<float2*>(a.hfinal + (size_t)r * HDIM + c) =
                        make_float2(hn[0], hn[1]);
            }
        }
    }
}

// ---------------- final dense(1024->3) + relu (sorted -> original order) ----------------
__global__ void dense_kernel(const float* __restrict__ hfinal,
                             const int* __restrict__ perm,
                             const float* __restrict__ Wd,
                             const float* __restrict__ bd,
                             float* __restrict__ out)
{
    const int bs = blockIdx.x;
    const float* h = hfinal + (size_t)bs * HDIM;

    float s0 = 0.f, s1 = 0.f, s2 = 0.f;
    for (int k = threadIdx.x; k < HDIM; k += blockDim.x) {
        float hv = h[k];
        s0 = fmaf(hv, Wd[k * 3 + 0], s0);
        s1 = fmaf(hv, Wd[k * 3 + 1], s1);
        s2 = fmaf(hv, Wd[k * 3 + 2], s2);
    }
    #pragma unroll
    for (int o = 16; o > 0; o >>= 1) {
        s0 += __shfl_down_sync(0xffffffffu, s0, o);
        s1 += __shfl_down_sync(0xffffffffu, s1, o);
        s2 += __shfl_down_sync(0xffffffffu, s2, o);
    }
    __shared__ float red[8][3];
    const int wid = threadIdx.x >> 5, lane = threadIdx.x & 31;
    if (lane == 0) { red[wid][0] = s0; red[wid][1] = s1; red[wid][2] = s2; }
    __syncthreads();
    if (threadIdx.x == 0) {
        float r0 = 0.f, r1 = 0.f, r2 = 0.f;
        const int nw = blockDim.x >> 5;
        for (int w = 0; w < nw; ++w) { r0 += red[w][0]; r1 += red[w][1]; r2 += red[w][2]; }
        const int b = perm[bs];
        out[b * 3 + 0] = fmaxf(r0 + bd[0], 0.f);
        out[b * 3 + 1] = fmaxf(r1 + bd[1], 0.f);
        out[b * 3 + 2] = fmaxf(r2 + bd[2], 0.f);
    }
}

extern "C" void kernel_launch(void* const* d_in, const int* in_sizes, int n_in,
                              void* d_out, int out_size) {
    const float* chars  = (const float*)d_in[0];
    const int*   seqlen = (const int*)  d_in[1];
    const float* W1 = (const float*)d_in[2];
    const float* U1 = (const float*)d_in[3];
    const float* b1 = (const float*)d_in[4];
    const float* W2 = (const float*)d_in[5];
    const float* U2 = (const float*)d_in[6];
    const float* b2 = (const float*)d_in[7];
    const float* Wd = (const float*)d_in[8];
    const float* bd = (const float*)d_in[9];
    float* out = (float*)d_out;

    char *xt, *h1t, *h2t, *w1t, *u1t, *w2t, *u2t;
    float *c1, *c2, *hfin;
    int *perm, *slen, *nact;
    cudaGetSymbolAddress((void**)&xt,   g_xt);
    cudaGetSymbolAddress((void**)&h1t,  g_h1t);
    cudaGetSymbolAddress((void**)&h2t,  g_h2t);
    cudaGetSymbolAddress((void**)&w1t,  g_w1t);
    cudaGetSymbolAddress((void**)&u1t,  g_u1t);
    cudaGetSymbolAddress((void**)&w2t,  g_w2t);
    cudaGetSymbolAddress((void**)&u2t,  g_u2t);
    cudaGetSymbolAddress((void**)&c1,   g_c1);
    cudaGetSymbolAddress((void**)&c2,   g_c2);
    cudaGetSymbolAddress((void**)&hfin, g_hfinal);
    cudaGetSymbolAddress((void**)&perm, g_perm);
    cudaGetSymbolAddress((void**)&slen, g_slen);
    cudaGetSymbolAddress((void**)&nact, g_nact);

    cudaFuncSetAttribute(lstm_step,
                         cudaFuncAttributeMaxDynamicSharedMemorySize, SMEM_BYTES);

    const size_t HSLOT = (size_t)8 * 32 * A_TILE_B;

    // prep (3 launches so ncu -s 5 lands on lstm_step)
    sort_rows<<<1, B_ROWS>>>(seqlen, perm, slen, nact);
    const int nx = B_ROWS * T_STEPS * DIM_IN;
    split_chars_tiled<<<(nx + 255) / 256, 256>>>(chars, perm, xt);
    {
        TransArgs t0 = {W1, w1t, DIM_IN};
        TransArgs t1 = {U1, u1t, HDIM};
        TransArgs t2 = {W2, w2t, HDIM};
        TransArgs t3 = {U2, u2t, HDIM};
        transpose_split_w_all<<<dim3(FOURH / 32, HDIM / 32, 4), dim3(32, 8)>>>(t0, t1, t2, t3);
    }

    auto mkL1 = [&](int t) {
        StepArgs s;
        const int prev = t & 1, cur = (t + 1) & 1;
        s.Ax = xt + (size_t)t * 8 * 8 * A_TILE_B;
        s.Hx = h1t + prev * HSLOT;
        s.Bw = w1t; s.Bu = u1t;
        s.KC0 = DIM_IN / 32;
        s.bias = b1; s.C = c1;
        s.Ot = h1t + cur * HSLOT;
        s.seqlen = nullptr; s.hfinal = nullptr;
        s.nact = nact;
        s.t = t; s.first = (t == 0) ? 1 : 0;
        return s;
    };
    auto mkL2 = [&](int t) {
        StepArgs s;
        const int prev = t & 1, cur = (t + 1) & 1;
        s.Ax = h1t + cur * HSLOT;
        s.Hx = h2t + prev * HSLOT;
        s.Bw = w2t; s.Bu = u2t;
        s.KC0 = HDIM / 32;
        s.bias = b2; s.C = c2;
        s.Ot = h2t + cur * HSLOT;
        s.seqlen = slen; s.hfinal = hfin;
        s.nact = nact;
        s.t = t; s.first = (t == 0) ? 1 : 0;
        return s;
    };

    const dim3 grid1(HDIM / BN, B_ROWS / BM, 1);
    const dim3 grid2(HDIM / BN, B_ROWS / BM, 2);

    {
        StepArgs s = mkL1(0);
        lstm_step<<<grid1, NTH, SMEM_BYTES>>>(s, s);
    }
    for (int k = 1; k < T_STEPS; ++k) {
        StepArgs sA = mkL1(k);
        StepArgs sB = mkL2(k - 1);
        lstm_step<<<grid2, NTH, SMEM_BYTES>>>(sA, sB);
    }
    {
        StepArgs s = mkL2(T_STEPS - 1);
        lstm_step<<<grid1, NTH, SMEM_BYTES>>>(s, s);
    }
    dense_kernel<<<B_ROWS, 256>>>(hfin, perm, Wd, bd, out);
}

// round 10
// speedup vs baseline: 1.1760x; 1.1760x over previous
#include <cuda_runtime.h>
#include <cuda_bf16.h>
#include <cstdint>
#include <math.h>

typedef __nv_bfloat16 bf16;

#define B_ROWS   512
#define T_STEPS  128
#define DIM_IN   256
#define HDIM     1024
#define FOURH    4096

#define BM 64
#define BN 32            // columns per gate per block
#define NTH 256          // 8 warps: 4 (m, 16 rows) x 2 (n, 16 cols)

// Tile images (gmem layout == smem layout):
// A tile: [2 planes][64 rows][80 B]          = 10240 B
// B tile: [2 planes][4*32 rows][80 B]        = 20480 B  (row = gate*32 + n_local)
#define A_TILE_B  10240
#define B_TILE_B  20480
#define A_PLANE_B 5120
#define B_PLANE_B 10240
#define STAGE_B   (A_TILE_B + B_TILE_B)      // 30720

// smem: [0..24) 3 mbarriers, stages at 1024
#define SM_A_OFF(s) (1024 + (s) * STAGE_B)
#define SM_B_OFF(s) (SM_A_OFF(s) + A_TILE_B)
#define SMEM_BYTES  (1024 + 3 * STAGE_B)     // 93184  -> 2 CTAs/SM

// ---------------- persistent device scratch (sorted row space) ----------------
__device__ __align__(128) char g_xt[(size_t)T_STEPS * 8 * 8 * A_TILE_B];
__device__ __align__(128) char g_h1t[2][(size_t)8 * 32 * A_TILE_B];
__device__ __align__(128) char g_h2t[2][(size_t)8 * 32 * A_TILE_B];
// tiled weights: [nblk(32)][kc(K/32)] tiles of B_TILE_B
__device__ __align__(128) char g_w1t[(size_t)32 * 8  * B_TILE_B];
__device__ __align__(128) char g_u1t[(size_t)32 * 32 * B_TILE_B];
__device__ __align__(128) char g_w2t[(size_t)32 * 32 * B_TILE_B];
__device__ __align__(128) char g_u2t[(size_t)32 * 32 * B_TILE_B];
__device__ float g_c1[(size_t)B_ROWS * HDIM];
__device__ float g_c2[(size_t)B_ROWS * HDIM];
__device__ float g_hfinal[(size_t)B_ROWS * HDIM];
__device__ int   g_perm[B_ROWS];
__device__ int   g_slen[B_ROWS];
__device__ int   g_nact[T_STEPS];

// ---------------- helpers ----------------
__device__ __forceinline__ uint32_t smem_u32(const void* p) {
    uint32_t a;
    asm("{ .reg .u64 t; cvta.to.shared.u64 t, %1; cvt.u32.u64 %0, t; }" : "=r"(a) : "l"(p));
    return a;
}
__device__ __forceinline__ void mbar_init(uint32_t a, uint32_t cnt) {
    asm volatile("mbarrier.init.shared.b64 [%0], %1;" :: "r"(a), "r"(cnt) : "memory");
}
__device__ __forceinline__ void mbar_expect(uint32_t a, uint32_t bytes) {
    asm volatile("mbarrier.arrive.expect_tx.shared.b64 _, [%0], %1;"
                 :: "r"(a), "r"(bytes) : "memory");
}
__device__ __forceinline__ void mbar_wait(uint32_t a, uint32_t parity) {
    asm volatile(
        "{\n\t.reg .pred P;\n\t"
        "WL_%=:\n\t"
        "mbarrier.try_wait.parity.acquire.cta.shared::cta.b64 P, [%0], %1, 0x989680;\n\t"
        "@P bra.uni WD_%=;\n\t"
        "bra.uni WL_%=;\n\t"
        "WD_%=:\n\t}"
        :: "r"(a), "r"(parity) : "memory");
}
__device__ __forceinline__ void bulk_g2s(uint32_t dst, const void* src,
                                         uint32_t bytes, uint32_t mbar) {
    asm volatile(
        "cp.async.bulk.shared::cluster.global.mbarrier::complete_tx::bytes "
        "[%0], [%1], %2, [%3];"
        :: "r"(dst), "l"(src), "r"(bytes), "r"(mbar) : "memory");
}
__device__ __forceinline__ void ldmx4(uint32_t* r, uint32_t a) {
    asm volatile("ldmatrix.sync.aligned.m8n8.x4.shared.b16 {%0,%1,%2,%3}, [%4];"
                 : "=r"(r[0]), "=r"(r[1]), "=r"(r[2]), "=r"(r[3]) : "r"(a));
}
__device__ __forceinline__ void ldmx2(uint32_t* r, uint32_t a) {
    asm volatile("ldmatrix.sync.aligned.m8n8.x2.shared.b16 {%0,%1}, [%2];"
                 : "=r"(r[0]), "=r"(r[1]) : "r"(a));
}
__device__ __forceinline__ void mma_bf16(float* d, const uint32_t* a, const uint32_t* b) {
    asm volatile(
        "mma.sync.aligned.m16n8k16.row.col.f32.bf16.bf16.f32 "
        "{%0,%1,%2,%3}, {%4,%5,%6,%7}, {%8,%9}, {%0,%1,%2,%3};"
        : "+f"(d[0]), "+f"(d[1]), "+f"(d[2]), "+f"(d[3])
        : "r"(a[0]), "r"(a[1]), "r"(a[2]), "r"(a[3]), "r"(b[0]), "r"(b[1]));
}
__device__ __forceinline__ float fsig(float x) { return 1.0f / (1.0f + __expf(-x)); }
__device__ __forceinline__ void split_bf16(float x, bf16& hi, bf16& lo) {
    hi = __float2bfloat16(x);
    lo = __float2bfloat16(x - __bfloat162float(hi));
}

// ---------------- prep kernels ----------------
__global__ void sort_rows(const int* __restrict__ seqlen,
                          int* __restrict__ perm, int* __restrict__ slen,
                          int* __restrict__ nact) {
    __shared__ int keys[B_ROWS];
    const int i = threadIdx.x;
    keys[i] = seqlen[i];
    __syncthreads();
    const int k = keys[i];
    int rank = 0;
    for (int j = 0; j < B_ROWS; ++j) {
        int kj = keys[j];
        rank += (kj > k) || (kj == k && j < i);
    }
    perm[rank] = i;
    slen[rank] = k;
    if (i < T_STEPS) {
        int cnt = 0;
        for (int j = 0; j < B_ROWS; ++j) cnt += (keys[j] >= i + 1);
        nact[i] = cnt;
    }
}

__global__ void split_chars_tiled(const float* __restrict__ x,
                                  const int* __restrict__ perm,
                                  char* __restrict__ xt) {
    const int n = B_ROWS * T_STEPS * DIM_IN;
    int i = blockIdx.x * blockDim.x + threadIdx.x;
    if (i >= n) return;
    const int row_elems = T_STEPS * DIM_IN;
    int bs = i / row_elems, d = i - bs * row_elems;
    int t = d >> 8, k = d & 255;
    float v = x[(size_t)perm[bs] * row_elems + d];
    bf16 h, l; split_bf16(v, h, l);
    size_t base = (((size_t)t * 8 + (bs >> 6)) * 8 + (k >> 5)) * A_TILE_B
                + (size_t)(bs & 63) * 80 + (k & 31) * 2;
    *reinterpret_cast<bf16*>(xt + base)             = h;
    *reinterpret_cast<bf16*>(xt + base + A_PLANE_B) = l;
}

// All four weight transposes in ONE launch (keeps lstm_step at launch index 3+).
struct TransArgs { const float* W; char* Wt; int K; };
__global__ void transpose_split_w_all(TransArgs t0, TransArgs t1,
                                      TransArgs t2, TransArgs t3) {
    TransArgs ta = (blockIdx.z == 0) ? t0
                 : (blockIdx.z == 1) ? t1
                 : (blockIdx.z == 2) ? t2 : t3;
    int kb = blockIdx.y * 32;
    if (kb >= ta.K) return;
    __shared__ float tile[32][33];
    int nb = blockIdx.x * 32;
    int x = threadIdx.x, y = threadIdx.y;
    #pragma unroll
    for (int yy = y; yy < 32; yy += 8)
        tile[yy][x] = ta.W[(size_t)(kb + yy) * FOURH + nb + x];
    __syncthreads();
    const int KC = ta.K >> 5;
    #pragma unroll
    for (int yy = y; yy < 32; yy += 8) {
        float w = tile[x][yy];
        bf16 h, l; split_bf16(w, h, l);
        int n4 = nb + yy, k = kb + x;
        int g = n4 >> 10, rr = n4 & 1023;
        int nblk = rr >> 5, nl = rr & 31;        // 32-wide n blocks
        int kc = k >> 5, kl = k & 31;
        size_t base = ((size_t)(nblk * KC + kc)) * B_TILE_B
                    + (size_t)(g * 32 + nl) * 80 + kl * 2;
        *reinterpret_cast<bf16*>(ta.Wt + base)             = h;
        *reinterpret_cast<bf16*>(ta.Wt + base + B_PLANE_B) = l;
    }
}

// ---------------- per-layer step arguments ----------------
struct StepArgs {
    const char* Ax;      // tiled X (A seg0), layout [rowblk][KC0]
    const char* Hx;      // tiled Hprev (A seg1), layout [rowblk][32]
    const char* Bw;      // tiled W (B seg0), layout [nblk][KC0]
    const char* Bu;      // tiled U (B seg1), layout [nblk][32]
    int KC0;
    const float* bias;
    float* C;
    char* Ot;            // tiled h output, layout [rowblk][32]
    const int* seqlen;
    float* hfinal;
    const int* nact;
    int t; int first;
};

// ---------------- fused dual-layer LSTM step (bf16x3, BN=32, 2 CTAs/SM) ----------
__global__ __launch_bounds__(NTH)
void lstm_step(const StepArgs a0, const StepArgs a1)
{
    const StepArgs a = (blockIdx.z == 0) ? a0 : a1;
    const int rowblk = blockIdx.y;
    const int row0 = rowblk * BM;
    if (row0 >= a.nact[a.t]) return;

    extern __shared__ char smemc[];
    const uint32_t sb = smem_u32(smemc);
    const int tid  = threadIdx.x;
    const int lane = tid & 31;
    const int warp = tid >> 5;
    const int wm   = warp >> 1;          // 0..3 -> 16-row slab
    const int wn   = warp & 1;           // 0..1 -> 16-col slab
    const int nblk = blockIdx.x;
    const int n0   = nblk * BN;

    const int arow  = (lane & 7) + ((lane >> 3) & 1) * 8;
    const int koffA = (lane >> 4) * 8;
    const int laneb = lane & 15;
    const int brow  = laneb & 7;
    const int koffB = ((laneb >> 3) & 1) * 8;

    float acc[4][2][4];                  // [gate][nt][frag]
    #pragma unroll
    for (int g = 0; g < 4; ++g)
        #pragma unroll
        for (int nt = 0; nt < 2; ++nt)
            #pragma unroll
            for (int q = 0; q < 4; ++q) acc[g][nt][q] = 0.f;

    const int KC0i = a.KC0;
    const int nch = a.first ? KC0i : (KC0i + 32);

    auto issue = [&](int c) {
        const int st = c % 3;
        const uint32_t mb = sb + st * 8;
        const int seg = (c < KC0i) ? 0 : 1;
        const int kc  = seg ? (c - KC0i) : c;
        const char* As = seg ? (a.Hx + ((size_t)(rowblk * 32 + kc)) * A_TILE_B)
                             : (a.Ax + ((size_t)(rowblk * KC0i + kc)) * A_TILE_B);
        const char* Bs = seg ? (a.Bu + ((size_t)(nblk * 32 + kc)) * B_TILE_B)
                             : (a.Bw + ((size_t)(nblk * KC0i + kc)) * B_TILE_B);
        mbar_expect(mb, STAGE_B);
        bulk_g2s(sb + SM_A_OFF(st), As, A_TILE_B, mb);
        bulk_g2s(sb + SM_B_OFF(st), Bs, B_TILE_B, mb);
    };

    if (tid == 0) {
        #pragma unroll
        for (int s = 0; s < 3; ++s) mbar_init(sb + s * 8, 1);
        asm volatile("fence.proxy.async.shared::cta;" ::: "memory");
        issue(0);
        if (nch > 1) issue(1);
    }
    __syncthreads();

    for (int i = 0; i < nch; ++i) {
        mbar_wait(sb + (i % 3) * 8, (uint32_t)((i / 3) & 1));
        __syncthreads();
        if (tid == 0 && i + 2 < nch) issue(i + 2);

        const int st = i % 3;
        const uint32_t aB = sb + SM_A_OFF(st);
        const uint32_t bB = sb + SM_B_OFF(st);

        #pragma unroll
        for (int ks = 0; ks < 2; ++ks) {
            uint32_t ah[4], al[4];
            uint32_t aa = aB + (uint32_t)((wm * 16 + arow) * 80 + (ks * 16 + koffA) * 2);
            ldmx4(ah, aa);
            ldmx4(al, aa + A_PLANE_B);
            #pragma unroll
            for (int g = 0; g < 4; ++g) {
                #pragma unroll
                for (int nt = 0; nt < 2; ++nt) {
                    uint32_t ba = bB + (uint32_t)((g * 32 + wn * 16 + nt * 8 + brow) * 80
                                                  + (ks * 16 + koffB) * 2);
                    uint32_t bh[2], bl[2];
                    ldmx2(bh, ba);
                    ldmx2(bl, ba + B_PLANE_B);
                    mma_bf16(acc[g][nt], ah, bh);
                    mma_bf16(acc[g][nt], ah, bl);
                    mma_bf16(acc[g][nt], al, bh);
                }
            }
        }
    }

    // ---- fused LSTM cell epilogue (h written in tiled A-image layout) ----
    #pragma unroll
    for (int half = 0; half < 2; ++half) {
        const int r = row0 + wm * 16 + half * 8 + (lane >> 2);
        const int slen = a.seqlen ? a.seqlen[r] : 0;
        #pragma unroll
        for (int nt = 0; nt < 2; ++nt) {
            const int c = n0 + wn * 16 + nt * 8 + (lane & 3) * 2;
            float2 cold = make_float2(0.f, 0.f);
            if (!a.first)
                cold = *reinterpret_cast<const float2*>(a.C + (size_t)r * HDIM + c);
            float cn[2], hn[2];
            #pragma unroll
            for (int j = 0; j < 2; ++j) {
                const int q = half * 2 + j;
                float zi = acc[0][nt][q] + a.bias[c + j];
                float zf = acc[1][nt][q] + a.bias[HDIM + c + j];
                float zg = acc[2][nt][q] + a.bias[2 * HDIM + c + j];
                float zo = acc[3][nt][q] + a.bias[3 * HDIM + c + j];
                float ig = fsig(zi), fg = fsig(zf);
                float gg = tanhf(zg), og = fsig(zo);
                float co = (j == 0) ? cold.x : cold.y;
                cn[j] = fmaf(fg, co, ig * gg);
                hn[j] = og * tanhf(cn[j]);
            }
            *reinterpret_cast<float2*>(a.C + (size_t)r * HDIM + c) = make_float2(cn[0], cn[1]);
            bf16 h0, l0, h1, l1;
            split_bf16(hn[0], h0, l0);
            split_bf16(hn[1], h1, l1);
            size_t toff = ((size_t)((r >> 6) * 32 + (c >> 5))) * A_TILE_B
                        + (size_t)(r & 63) * 80 + (c & 31) * 2;
            *reinterpret_cast<__nv_bfloat162*>(a.Ot + toff) = __nv_bfloat162(h0, h1);
            *reinterpret_cast<__nv_bfloat162*>(a.Ot + toff + A_PLANE_B) =
                __nv_bfloat162(l0, l1);
            if (a.hfinal && slen - 1 == a.t)
                *reinterpret_cast<float2*>(a.hfinal + (size_t)r * HDIM + c) =
                    make_float2(hn[0], hn[1]);
        }
    }
}

// ---------------- final dense(1024->3) + relu (sorted -> original order) ----------------
__global__ void dense_kernel(const float* __restrict__ hfinal,
                             const int* __restrict__ perm,
                             const float* __restrict__ Wd,
                             const float* __restrict__ bd,
                             float* __restrict__ out)
{
    const int bs = blockIdx.x;
    const float* h = hfinal + (size_t)bs * HDIM;

    float s0 = 0.f, s1 = 0.f, s2 = 0.f;
    for (int k = threadIdx.x; k < HDIM; k += blockDim.x) {
        float hv = h[k];
        s0 = fmaf(hv, Wd[k * 3 + 0], s0);
        s1 = fmaf(hv, Wd[k * 3 + 1], s1);
        s2 = fmaf(hv, Wd[k * 3 + 2], s2);
    }
    #pragma unroll
    for (int o = 16; o > 0; o >>= 1) {
        s0 += __shfl_down_sync(0xffffffffu, s0, o);
        s1 += __shfl_down_sync(0xffffffffu, s1, o);
        s2 += __shfl_down_sync(0xffffffffu, s2, o);
    }
    __shared__ float red[8][3];
    const int wid = threadIdx.x >> 5, lane = threadIdx.x & 31;
    if (lane == 0) { red[wid][0] = s0; red[wid][1] = s1; red[wid][2] = s2; }
    __syncthreads();
    if (threadIdx.x == 0) {
        float r0 = 0.f, r1 = 0.f, r2 = 0.f;
        const int nw = blockDim.x >> 5;
        for (int w = 0; w < nw; ++w) { r0 += red[w][0]; r1 += red[w][1]; r2 += red[w][2]; }
        const int b = perm[bs];
        out[b * 3 + 0] = fmaxf(r0 + bd[0], 0.f);
        out[b * 3 + 1] = fmaxf(r1 + bd[1], 0.f);
        out[b * 3 + 2] = fmaxf(r2 + bd[2], 0.f);
    }
}

extern "C" void kernel_launch(void* const* d_in, const int* in_sizes, int n_in,
                              void* d_out, int out_size) {
    const float* chars  = (const float*)d_in[0];
    const int*   seqlen = (const int*)  d_in[1];
    const float* W1 = (const float*)d_in[2];
    const float* U1 = (const float*)d_in[3];
    const float* b1 = (const float*)d_in[4];
    const float* W2 = (const float*)d_in[5];
    const float* U2 = (const float*)d_in[6];
    const float* b2 = (const float*)d_in[7];
    const float* Wd = (const float*)d_in[8];
    const float* bd = (const float*)d_in[9];
    float* out = (float*)d_out;

    char *xt, *h1t, *h2t, *w1t, *u1t, *w2t, *u2t;
    float *c1, *c2, *hfin;
    int *perm, *slen, *nact;
    cudaGetSymbolAddress((void**)&xt,   g_xt);
    cudaGetSymbolAddress((void**)&h1t,  g_h1t);
    cudaGetSymbolAddress((void**)&h2t,  g_h2t);
    cudaGetSymbolAddress((void**)&w1t,  g_w1t);
    cudaGetSymbolAddress((void**)&u1t,  g_u1t);
    cudaGetSymbolAddress((void**)&w2t,  g_w2t);
    cudaGetSymbolAddress((void**)&u2t,  g_u2t);
    cudaGetSymbolAddress((void**)&c1,   g_c1);
    cudaGetSymbolAddress((void**)&c2,   g_c2);
    cudaGetSymbolAddress((void**)&hfin, g_hfinal);
    cudaGetSymbolAddress((void**)&perm, g_perm);
    cudaGetSymbolAddress((void**)&slen, g_slen);
    cudaGetSymbolAddress((void**)&nact, g_nact);

    cudaFuncSetAttribute(lstm_step,
                         cudaFuncAttributeMaxDynamicSharedMemorySize, SMEM_BYTES);

    const size_t HSLOT = (size_t)8 * 32 * A_TILE_B;

    // prep (3 launches so ncu -s 5 lands on lstm_step)
    sort_rows<<<1, B_ROWS>>>(seqlen, perm, slen, nact);
    const int nx = B_ROWS * T_STEPS * DIM_IN;
    split_chars_tiled<<<(nx + 255) / 256, 256>>>(chars, perm, xt);
    {
        TransArgs t0 = {W1, w1t, DIM_IN};
        TransArgs t1 = {U1, u1t, HDIM};
        TransArgs t2 = {W2, w2t, HDIM};
        TransArgs t3 = {U2, u2t, HDIM};
        transpose_split_w_all<<<dim3(FOURH / 32, HDIM / 32, 4), dim3(32, 8)>>>(t0, t1, t2, t3);
    }

    auto mkL1 = [&](int t) {
        StepArgs s;
        const int prev = t & 1, cur = (t + 1) & 1;
        s.Ax = xt + (size_t)t * 8 * 8 * A_TILE_B;
        s.Hx = h1t + prev * HSLOT;
        s.Bw = w1t; s.Bu = u1t;
        s.KC0 = DIM_IN / 32;
        s.bias = b1; s.C = c1;
        s.Ot = h1t + cur * HSLOT;
        s.seqlen = nullptr; s.hfinal = nullptr;
        s.nact = nact;
        s.t = t; s.first = (t == 0) ? 1 : 0;
        return s;
    };
    auto mkL2 = [&](int t) {
        StepArgs s;
        const int prev = t & 1, cur = (t + 1) & 1;
        s.Ax = h1t + cur * HSLOT;
        s.Hx = h2t + prev * HSLOT;
        s.Bw = w2t; s.Bu = u2t;
        s.KC0 = HDIM / 32;
        s.bias = b2; s.C = c2;
        s.Ot = h2t + cur * HSLOT;
        s.seqlen = slen; s.hfinal = hfin;
        s.nact = nact;
        s.t = t; s.first = (t == 0) ? 1 : 0;
        return s;
    };

    const dim3 grid1(HDIM / BN, B_ROWS / BM, 1);   // (32, 8, 1)
    const dim3 grid2(HDIM / BN, B_ROWS / BM, 2);   // (32, 8, 2)

    {
        StepArgs s = mkL1(0);
        lstm_step<<<grid1, NTH, SMEM_BYTES>>>(s, s);
    }
    for (int k = 1; k < T_STEPS; ++k) {
        StepArgs sA = mkL1(k);
        StepArgs sB = mkL2(k - 1);
        lstm_step<<<grid2, NTH, SMEM_BYTES>>>(sA, sB);
    }
    {
        StepArgs s = mkL2(T_STEPS - 1);
        lstm_step<<<grid1, NTH, SMEM_BYTES>>>(s, s);
    }
    dense_kernel<<<B_ROWS, 256>>>(hfin, perm, Wd, bd, out);
}

// round 11
// speedup vs baseline: 1.3234x; 1.1253x over previous
#include <cuda_runtime.h>
#include <cuda_bf16.h>
#include <cstdint>
#include <math.h>

typedef __nv_bfloat16 bf16;

#define B_ROWS   512
#define T_STEPS  128
#define DIM_IN   256
#define HDIM     1024
#define FOURH    4096

#define BM 64
#define BN 32            // columns per gate per block
#define NCONS 256        // 8 consumer warps: 4 (m) x 2 (n)
#define NTH 288          // + 1 producer warp

// Tile images (gmem layout == smem layout):
#define A_TILE_B  10240
#define B_TILE_B  20480
#define A_PLANE_B 5120
#define B_PLANE_B 10240
#define STAGE_B   (A_TILE_B + B_TILE_B)      // 30720

// smem: [0..24) full mbarriers, [24..48) empty mbarriers, stages at 1024
#define SM_FULL(s)  ((s) * 8)
#define SM_EMPTY(s) (24 + (s) * 8)
#define SM_A_OFF(s) (1024 + (s) * STAGE_B)
#define SM_B_OFF(s) (SM_A_OFF(s) + A_TILE_B)
#define SMEM_BYTES  (1024 + 3 * STAGE_B)     // 93184 -> 2 CTAs/SM

// ---------------- persistent device scratch (sorted row space) ----------------
__device__ __align__(128) char g_xt[(size_t)T_STEPS * 8 * 8 * A_TILE_B];
__device__ __align__(128) char g_h1t[2][(size_t)8 * 32 * A_TILE_B];
__device__ __align__(128) char g_h2t[2][(size_t)8 * 32 * A_TILE_B];
__device__ __align__(128) char g_w1t[(size_t)32 * 8  * B_TILE_B];
__device__ __align__(128) char g_u1t[(size_t)32 * 32 * B_TILE_B];
__device__ __align__(128) char g_w2t[(size_t)32 * 32 * B_TILE_B];
__device__ __align__(128) char g_u2t[(size_t)32 * 32 * B_TILE_B];
__device__ float g_c1[(size_t)B_ROWS * HDIM];
__device__ float g_c2[(size_t)B_ROWS * HDIM];
__device__ float g_hfinal[(size_t)B_ROWS * HDIM];
__device__ int   g_perm[B_ROWS];
__device__ int   g_slen[B_ROWS];
__device__ int   g_nact[T_STEPS];

// ---------------- helpers ----------------
__device__ __forceinline__ uint32_t smem_u32(const void* p) {
    uint32_t a;
    asm("{ .reg .u64 t; cvta.to.shared.u64 t, %1; cvt.u32.u64 %0, t; }" : "=r"(a) : "l"(p));
    return a;
}
__device__ __forceinline__ void mbar_init(uint32_t a, uint32_t cnt) {
    asm volatile("mbarrier.init.shared.b64 [%0], %1;" :: "r"(a), "r"(cnt) : "memory");
}
__device__ __forceinline__ void mbar_expect(uint32_t a, uint32_t bytes) {
    asm volatile("mbarrier.arrive.expect_tx.shared.b64 _, [%0], %1;"
                 :: "r"(a), "r"(bytes) : "memory");
}
__device__ __forceinline__ void mbar_arrive(uint32_t a) {
    asm volatile("mbarrier.arrive.shared.b64 _, [%0];" :: "r"(a) : "memory");
}
__device__ __forceinline__ void mbar_wait(uint32_t a, uint32_t parity) {
    asm volatile(
        "{\n\t.reg .pred P;\n\t"
        "WL_%=:\n\t"
        "mbarrier.try_wait.parity.acquire.cta.shared::cta.b64 P, [%0], %1, 0x989680;\n\t"
        "@P bra.uni WD_%=;\n\t"
        "bra.uni WL_%=;\n\t"
        "WD_%=:\n\t}"
        :: "r"(a), "r"(parity) : "memory");
}
__device__ __forceinline__ void bulk_g2s(uint32_t dst, const void* src,
                                         uint32_t bytes, uint32_t mbar) {
    asm volatile(
        "cp.async.bulk.shared::cluster.global.mbarrier::complete_tx::bytes "
        "[%0], [%1], %2, [%3];"
        :: "r"(dst), "l"(src), "r"(bytes), "r"(mbar) : "memory");
}
__device__ __forceinline__ void ldmx4(uint32_t* r, uint32_t a) {
    asm volatile("ldmatrix.sync.aligned.m8n8.x4.shared.b16 {%0,%1,%2,%3}, [%4];"
                 : "=r"(r[0]), "=r"(r[1]), "=r"(r[2]), "=r"(r[3]) : "r"(a));
}
__device__ __forceinline__ void ldmx2(uint32_t* r, uint32_t a) {
    asm volatile("ldmatrix.sync.aligned.m8n8.x2.shared.b16 {%0,%1}, [%2];"
                 : "=r"(r[0]), "=r"(r[1]) : "r"(a));
}
__device__ __forceinline__ void mma_bf16(float* d, const uint32_t* a, const uint32_t* b) {
    asm volatile(
        "mma.sync.aligned.m16n8k16.row.col.f32.bf16.bf16.f32 "
        "{%0,%1,%2,%3}, {%4,%5,%6,%7}, {%8,%9}, {%0,%1,%2,%3};"
        : "+f"(d[0]), "+f"(d[1]), "+f"(d[2]), "+f"(d[3])
        : "r"(a[0]), "r"(a[1]), "r"(a[2]), "r"(a[3]), "r"(b[0]), "r"(b[1]));
}
__device__ __forceinline__ float fsig(float x) { return 1.0f / (1.0f + __expf(-x)); }
__device__ __forceinline__ void split_bf16(float x, bf16& hi, bf16& lo) {
    hi = __float2bfloat16(x);
    lo = __float2bfloat16(x - __bfloat162float(hi));
}

// ---------------- prep kernels ----------------
__global__ void sort_rows(const int* __restrict__ seqlen,
                          int* __restrict__ perm, int* __restrict__ slen,
                          int* __restrict__ nact) {
    __shared__ int keys[B_ROWS];
    const int i = threadIdx.x;
    keys[i] = seqlen[i];
    __syncthreads();
    const int k = keys[i];
    int rank = 0;
    for (int j = 0; j < B_ROWS; ++j) {
        int kj = keys[j];
        rank += (kj > k) || (kj == k && j < i);
    }
    perm[rank] = i;
    slen[rank] = k;
    if (i < T_STEPS) {
        int cnt = 0;
        for (int j = 0; j < B_ROWS; ++j) cnt += (keys[j] >= i + 1);
        nact[i] = cnt;
    }
}

__global__ void split_chars_tiled(const float* __restrict__ x,
                                  const int* __restrict__ perm,
                                  char* __restrict__ xt) {
    const int n = B_ROWS * T_STEPS * DIM_IN;
    int i = blockIdx.x * blockDim.x + threadIdx.x;
    if (i >= n) return;
    const int row_elems = T_STEPS * DIM_IN;
    int bs = i / row_elems, d = i - bs * row_elems;
    int t = d >> 8, k = d & 255;
    float v = x[(size_t)perm[bs] * row_elems + d];
    bf16 h, l; split_bf16(v, h, l);
    size_t base = (((size_t)t * 8 + (bs >> 6)) * 8 + (k >> 5)) * A_TILE_B
                + (size_t)(bs & 63) * 80 + (k & 31) * 2;
    *reinterpret_cast<bf16*>(xt + base)             = h;
    *reinterpret_cast<bf16*>(xt + base + A_PLANE_B) = l;
}

struct TransArgs { const float* W; char* Wt; int K; };
__global__ void transpose_split_w_all(TransArgs t0, TransArgs t1,
                                      TransArgs t2, TransArgs t3) {
    TransArgs ta = (blockIdx.z == 0) ? t0
                 : (blockIdx.z == 1) ? t1
                 : (blockIdx.z == 2) ? t2 : t3;
    int kb = blockIdx.y * 32;
    if (kb >= ta.K) return;
    __shared__ float tile[32][33];
    int nb = blockIdx.x * 32;
    int x = threadIdx.x, y = threadIdx.y;
    #pragma unroll
    for (int yy = y; yy < 32; yy += 8)
        tile[yy][x] = ta.W[(size_t)(kb + yy) * FOURH + nb + x];
    __syncthreads();
    const int KC = ta.K >> 5;
    #pragma unroll
    for (int yy = y; yy < 32; yy += 8) {
        float w = tile[x][yy];
        bf16 h, l; split_bf16(w, h, l);
        int n4 = nb + yy, k = kb + x;
        int g = n4 >> 10, rr = n4 & 1023;
        int nblk = rr >> 5, nl = rr & 31;
        int kc = k >> 5, kl = k & 31;
        size_t base = ((size_t)(nblk * KC + kc)) * B_TILE_B
                    + (size_t)(g * 32 + nl) * 80 + kl * 2;
        *reinterpret_cast<bf16*>(ta.Wt + base)             = h;
        *reinterpret_cast<bf16*>(ta.Wt + base + B_PLANE_B) = l;
    }
}

// ---------------- per-layer step arguments ----------------
struct StepArgs {
    const char* Ax;
    const char* Hx;
    const char* Bw;
    const char* Bu;
    int KC0;
    const float* bias;
    float* C;
    char* Ot;
    const int* seqlen;
    float* hfinal;
    const int* nact;
    int t; int first;
};

// ------- fused dual-layer LSTM step: warp-specialized producer/consumer -------
__global__ __launch_bounds__(NTH)
void lstm_step(const StepArgs a0, const StepArgs a1)
{
    const StepArgs a = (blockIdx.z == 0) ? a0 : a1;
    const int rowblk = blockIdx.y;
    const int row0 = rowblk * BM;
    if (row0 >= a.nact[a.t]) return;

    extern __shared__ char smemc[];
    const uint32_t sb = smem_u32(smemc);
    const int tid  = threadIdx.x;
    const int lane = tid & 31;
    const int warp = tid >> 5;
    const int nblk = blockIdx.x;
    const int n0   = nblk * BN;

    const int KC0i = a.KC0;
    const int nch = a.first ? KC0i : (KC0i + 32);

    if (tid == 0) {
        #pragma unroll
        for (int s = 0; s < 3; ++s) {
            mbar_init(sb + SM_FULL(s), 1);    // producer's expect_tx arrival
            mbar_init(sb + SM_EMPTY(s), 8);   // one arrival per consumer warp
        }
        asm volatile("fence.proxy.async.shared::cta;" ::: "memory");
    }
    __syncthreads();

    if (warp == 8) {
        // ---------------- producer warp ----------------
        if (lane == 0) {
            for (int c = 0; c < nch; ++c) {
                const int st = c % 3;
                if (c >= 3)
                    mbar_wait(sb + SM_EMPTY(st), (uint32_t)(((c / 3) - 1) & 1));
                const int seg = (c < KC0i) ? 0 : 1;
                const int kc  = seg ? (c - KC0i) : c;
                const char* As = seg ? (a.Hx + ((size_t)(rowblk * 32 + kc)) * A_TILE_B)
                                     : (a.Ax + ((size_t)(rowblk * KC0i + kc)) * A_TILE_B);
                const char* Bs = seg ? (a.Bu + ((size_t)(nblk * 32 + kc)) * B_TILE_B)
                                     : (a.Bw + ((size_t)(nblk * KC0i + kc)) * B_TILE_B);
                const uint32_t mb = sb + SM_FULL(st);
                mbar_expect(mb, STAGE_B);
                bulk_g2s(sb + SM_A_OFF(st), As, A_TILE_B, mb);
                bulk_g2s(sb + SM_B_OFF(st), Bs, B_TILE_B, mb);
            }
        }
        return;
    }

    // ---------------- consumer warps (0..7) ----------------
    const int wm = warp >> 1;            // 0..3 -> 16-row slab
    const int wn = warp & 1;             // 0..1 -> 16-col slab

    const int arow  = (lane & 7) + ((lane >> 3) & 1) * 8;
    const int koffA = (lane >> 4) * 8;
    const int laneb = lane & 15;
    const int brow  = laneb & 7;
    const int koffB = ((laneb >> 3) & 1) * 8;

    float acc[4][2][4];
    #pragma unroll
    for (int g = 0; g < 4; ++g)
        #pragma unroll
        for (int nt = 0; nt < 2; ++nt)
            #pragma unroll
            for (int q = 0; q < 4; ++q) acc[g][nt][q] = 0.f;

    for (int i = 0; i < nch; ++i) {
        const int st = i % 3;
        mbar_wait(sb + SM_FULL(st), (uint32_t)((i / 3) & 1));

        const uint32_t aB = sb + SM_A_OFF(st);
        const uint32_t bB = sb + SM_B_OFF(st);

        #pragma unroll
        for (int ks = 0; ks < 2; ++ks) {
            uint32_t ah[4], al[4];
            uint32_t aa = aB + (uint32_t)((wm * 16 + arow) * 80 + (ks * 16 + koffA) * 2);
            ldmx4(ah, aa);
            ldmx4(al, aa + A_PLANE_B);
            #pragma unroll
            for (int g = 0; g < 4; ++g) {
                #pragma unroll
                for (int nt = 0; nt < 2; ++nt) {
                    uint32_t ba = bB + (uint32_t)((g * 32 + wn * 16 + nt * 8 + brow) * 80
                                                  + (ks * 16 + koffB) * 2);
                    uint32_t bh[2], bl[2];
                    ldmx2(bh, ba);
                    ldmx2(bl, ba + B_PLANE_B);
                    mma_bf16(acc[g][nt], ah, bh);
                    mma_bf16(acc[g][nt], ah, bl);
                    mma_bf16(acc[g][nt], al, bh);
                }
            }
        }
        __syncwarp();
        if (lane == 0) mbar_arrive(sb + SM_EMPTY(st));
    }

    // ---- fused LSTM cell epilogue (h written in tiled A-image layout) ----
    #pragma unroll
    for (int half = 0; half < 2; ++half) {
        const int r = row0 + wm * 16 + half * 8 + (lane >> 2);
        const int slen = a.seqlen ? a.seqlen[r] : 0;
        #pragma unroll
        for (int nt = 0; nt < 2; ++nt) {
            const int c = n0 + wn * 16 + nt * 8 + (lane & 3) * 2;
            float2 cold = make_float2(0.f, 0.f);
            if (!a.first)
                cold = *reinterpret_cast<const float2*>(a.C + (size_t)r * HDIM + c);
            float cn[2], hn[2];
            #pragma unroll
            for (int j = 0; j < 2; ++j) {
                const int q = half * 2 + j;
                float zi = acc[0][nt][q] + a.bias[c + j];
                float zf = acc[1][nt][q] + a.bias[HDIM + c + j];
                float zg = acc[2][nt][q] + a.bias[2 * HDIM + c + j];
                float zo = acc[3][nt][q] + a.bias[3 * HDIM + c + j];
                float ig = fsig(zi), fg = fsig(zf);
                float gg = tanhf(zg), og = fsig(zo);
                float co = (j == 0) ? cold.x : cold.y;
                cn[j] = fmaf(fg, co, ig * gg);
                hn[j] = og * tanhf(cn[j]);
            }
            *reinterpret_cast<float2*>(a.C + (size_t)r * HDIM + c) = make_float2(cn[0], cn[1]);
            bf16 h0, l0, h1, l1;
            split_bf16(hn[0], h0, l0);
            split_bf16(hn[1], h1, l1);
            size_t toff = ((size_t)((r >> 6) * 32 + (c >> 5))) * A_TILE_B
                        + (size_t)(r & 63) * 80 + (c & 31) * 2;
            *reinterpret_cast<__nv_bfloat162*>(a.Ot + toff) = __nv_bfloat162(h0, h1);
            *reinterpret_cast<__nv_bfloat162*>(a.Ot + toff + A_PLANE_B) =
                __nv_bfloat162(l0, l1);
            if (a.hfinal && slen - 1 == a.t)
                *reinterpret_cast<float2*>(a.hfinal + (size_t)r * HDIM + c) =
                    make_float2(hn[0], hn[1]);
        }
    }
}

// ---------------- final dense(1024->3) + relu (sorted -> original order) ----------------
__global__ void dense_kernel(const float* __restrict__ hfinal,
                             const int* __restrict__ perm,
                             const float* __restrict__ Wd,
                             const float* __restrict__ bd,
                             float* __restrict__ out)
{
    const int bs = blockIdx.x;
    const float* h = hfinal + (size_t)bs * HDIM;

    float s0 = 0.f, s1 = 0.f, s2 = 0.f;
    for (int k = threadIdx.x; k < HDIM; k += blockDim.x) {
        float hv = h[k];
        s0 = fmaf(hv, Wd[k * 3 + 0], s0);
        s1 = fmaf(hv, Wd[k * 3 + 1], s1);
        s2 = fmaf(hv, Wd[k * 3 + 2], s2);
    }
    #pragma unroll
    for (int o = 16; o > 0; o >>= 1) {
        s0 += __shfl_down_sync(0xffffffffu, s0, o);
        s1 += __shfl_down_sync(0xffffffffu, s1, o);
        s2 += __shfl_down_sync(0xffffffffu, s2, o);
    }
    __shared__ float red[8][3];
    const int wid = threadIdx.x >> 5, lane = threadIdx.x & 31;
    if (lane == 0) { red[wid][0] = s0; red[wid][1] = s1; red[wid][2] = s2; }
    __syncthreads();
    if (threadIdx.x == 0) {
        float r0 = 0.f, r1 = 0.f, r2 = 0.f;
        const int nw = blockDim.x >> 5;
        for (int w = 0; w < nw; ++w) { r0 += red[w][0]; r1 += red[w][1]; r2 += red[w][2]; }
        const int b = perm[bs];
        out[b * 3 + 0] = fmaxf(r0 + bd[0], 0.f);
        out[b * 3 + 1] = fmaxf(r1 + bd[1], 0.f);
        out[b * 3 + 2] = fmaxf(r2 + bd[2], 0.f);
    }
}

extern "C" void kernel_launch(void* const* d_in, const int* in_sizes, int n_in,
                              void* d_out, int out_size) {
    const float* chars  = (const float*)d_in[0];
    const int*   seqlen = (const int*)  d_in[1];
    const float* W1 = (const float*)d_in[2];
    const float* U1 = (const float*)d_in[3];
    const float* b1 = (const float*)d_in[4];
    const float* W2 = (const float*)d_in[5];
    const float* U2 = (const float*)d_in[6];
    const float* b2 = (const float*)d_in[7];
    const float* Wd = (const float*)d_in[8];
    const float* bd = (const float*)d_in[9];
    float* out = (float*)d_out;

    char *xt, *h1t, *h2t, *w1t, *u1t, *w2t, *u2t;
    float *c1, *c2, *hfin;
    int *perm, *slen, *nact;
    cudaGetSymbolAddress((void**)&xt,   g_xt);
    cudaGetSymbolAddress((void**)&h1t,  g_h1t);
    cudaGetSymbolAddress((void**)&h2t,  g_h2t);
    cudaGetSymbolAddress((void**)&w1t,  g_w1t);
    cudaGetSymbolAddress((void**)&u1t,  g_u1t);
    cudaGetSymbolAddress((void**)&w2t,  g_w2t);
    cudaGetSymbolAddress((void**)&u2t,  g_u2t);
    cudaGetSymbolAddress((void**)&c1,   g_c1);
    cudaGetSymbolAddress((void**)&c2,   g_c2);
    cudaGetSymbolAddress((void**)&hfin, g_hfinal);
    cudaGetSymbolAddress((void**)&perm, g_perm);
    cudaGetSymbolAddress((void**)&slen, g_slen);
    cudaGetSymbolAddress((void**)&nact, g_nact);

    cudaFuncSetAttribute(lstm_step,
                         cudaFuncAttributeMaxDynamicSharedMemorySize, SMEM_BYTES);

    const size_t HSLOT = (size_t)8 * 32 * A_TILE_B;

    // prep (3 launches so ncu -s 5 lands on lstm_step)
    sort_rows<<<1, B_ROWS>>>(seqlen, perm, slen, nact);
    const int nx = B_ROWS * T_STEPS * DIM_IN;
    split_chars_tiled<<<(nx + 255) / 256, 256>>>(chars, perm, xt);
    {
        TransArgs t0 = {W1, w1t, DIM_IN};
        TransArgs t1 = {U1, u1t, HDIM};
        TransArgs t2 = {W2, w2t, HDIM};
        TransArgs t3 = {U2, u2t, HDIM};
        transpose_split_w_all<<<dim3(FOURH / 32, HDIM / 32, 4), dim3(32, 8)>>>(t0, t1, t2, t3);
    }

    auto mkL1 = [&](int t) {
        StepArgs s;
        const int prev = t & 1, cur = (t + 1) & 1;
        s.Ax = xt + (size_t)t * 8 * 8 * A_TILE_B;
        s.Hx = h1t + prev * HSLOT;
        s.Bw = w1t; s.Bu = u1t;
        s.KC0 = DIM_IN / 32;
        s.bias = b1; s.C = c1;
        s.Ot = h1t + cur * HSLOT;
        s.seqlen = nullptr; s.hfinal = nullptr;
        s.nact = nact;
        s.t = t; s.first = (t == 0) ? 1 : 0;
        return s;
    };
    auto mkL2 = [&](int t) {
        StepArgs s;
        const int prev = t & 1, cur = (t + 1) & 1;
        s.Ax = h1t + cur * HSLOT;
        s.Hx = h2t + prev * HSLOT;
        s.Bw = w2t; s.Bu = u2t;
        s.KC0 = HDIM / 32;
        s.bias = b2; s.C = c2;
        s.Ot = h2t + cur * HSLOT;
        s.seqlen = slen; s.hfinal = hfin;
        s.nact = nact;
        s.t = t; s.first = (t == 0) ? 1 : 0;
        return s;
    };

    const dim3 grid1(HDIM / BN, B_ROWS / BM, 1);   // (32, 8, 1)
    const dim3 grid2(HDIM / BN, B_ROWS / BM, 2);   // (32, 8, 2)

    {
        StepArgs s = mkL1(0);
        lstm_step<<<grid1, NTH, SMEM_BYTES>>>(s, s);
    }
    for (int k = 1; k < T_STEPS; ++k) {
        StepArgs sA = mkL1(k);
        StepArgs sB = mkL2(k - 1);
        lstm_step<<<grid2, NTH, SMEM_BYTES>>>(sA, sB);
    }
    {
        StepArgs s = mkL2(T_STEPS - 1);
        lstm_step<<<grid1, NTH, SMEM_BYTES>>>(s, s);
    }
    dense_kernel<<<B_ROWS, 256>>>(hfin, perm, Wd, bd, out);
}

// round 12
// speedup vs baseline: 1.3772x; 1.0406x over previous
#include <cuda_runtime.h>
#include <cuda_bf16.h>
#include <cstdint>
#include <math.h>

typedef __nv_bfloat16 bf16;

#define B_ROWS   512
#define T_STEPS  128
#define DIM_IN   256
#define HDIM     1024
#define FOURH    4096

#define BM 64
#define BN 32            // columns per gate per block
#define NCONS 256        // 8 consumer warps: 4 (m) x 2 (n)
#define NTH 288          // + 1 producer warp

// Tile images (gmem layout == smem layout):
#define A_TILE_B  10240
#define B_TILE_B  20480
#define A_PLANE_B 5120
#define B_PLANE_B 10240
#define STAGE_B   (A_TILE_B + B_TILE_B)      // 30720

// smem: [0..24) full mbarriers, [24..48) empty mbarriers, stages at 1024
#define SM_FULL(s)  ((s) * 8)
#define SM_EMPTY(s) (24 + (s) * 8)
#define SM_A_OFF(s) (1024 + (s) * STAGE_B)
#define SM_B_OFF(s) (SM_A_OFF(s) + A_TILE_B)
#define SMEM_BYTES  (1024 + 3 * STAGE_B)     // 93184 -> 2 CTAs/SM

// ---------------- persistent device scratch (sorted row space) ----------------
__device__ __align__(128) char g_xt[(size_t)T_STEPS * 8 * 8 * A_TILE_B];
__device__ __align__(128) char g_h1t[2][(size_t)8 * 32 * A_TILE_B];
__device__ __align__(128) char g_h2t[2][(size_t)8 * 32 * A_TILE_B];
__device__ __align__(128) char g_w1t[(size_t)32 * 8  * B_TILE_B];
__device__ __align__(128) char g_u1t[(size_t)32 * 32 * B_TILE_B];
__device__ __align__(128) char g_w2t[(size_t)32 * 32 * B_TILE_B];
__device__ __align__(128) char g_u2t[(size_t)32 * 32 * B_TILE_B];
__device__ float g_c1[(size_t)B_ROWS * HDIM];
__device__ float g_c2[(size_t)B_ROWS * HDIM];
__device__ float g_hfinal[(size_t)B_ROWS * HDIM];
__device__ int   g_perm[B_ROWS];
__device__ int   g_slen[B_ROWS];
__device__ int   g_nact[T_STEPS];

// ---------------- helpers ----------------
__device__ __forceinline__ uint32_t smem_u32(const void* p) {
    uint32_t a;
    asm("{ .reg .u64 t; cvta.to.shared.u64 t, %1; cvt.u32.u64 %0, t; }" : "=r"(a) : "l"(p));
    return a;
}
__device__ __forceinline__ void mbar_init(uint32_t a, uint32_t cnt) {
    asm volatile("mbarrier.init.shared.b64 [%0], %1;" :: "r"(a), "r"(cnt) : "memory");
}
__device__ __forceinline__ void mbar_expect(uint32_t a, uint32_t bytes) {
    asm volatile("mbarrier.arrive.expect_tx.shared.b64 _, [%0], %1;"
                 :: "r"(a), "r"(bytes) : "memory");
}
__device__ __forceinline__ void mbar_arrive(uint32_t a) {
    asm volatile("mbarrier.arrive.shared.b64 _, [%0];" :: "r"(a) : "memory");
}
__device__ __forceinline__ void mbar_wait(uint32_t a, uint32_t parity) {
    asm volatile(
        "{\n\t.reg .pred P;\n\t"
        "WL_%=:\n\t"
        "mbarrier.try_wait.parity.acquire.cta.shared::cta.b64 P, [%0], %1, 0x989680;\n\t"
        "@P bra.uni WD_%=;\n\t"
        "bra.uni WL_%=;\n\t"
        "WD_%=:\n\t}"
        :: "r"(a), "r"(parity) : "memory");
}
__device__ __forceinline__ void bulk_g2s(uint32_t dst, const void* src,
                                         uint32_t bytes, uint32_t mbar) {
    asm volatile(
        "cp.async.bulk.shared::cluster.global.mbarrier::complete_tx::bytes "
        "[%0], [%1], %2, [%3];"
        :: "r"(dst), "l"(src), "r"(bytes), "r"(mbar) : "memory");
}
__device__ __forceinline__ void ldmx4(uint32_t* r, uint32_t a) {
    asm volatile("ldmatrix.sync.aligned.m8n8.x4.shared.b16 {%0,%1,%2,%3}, [%4];"
                 : "=r"(r[0]), "=r"(r[1]), "=r"(r[2]), "=r"(r[3]) : "r"(a));
}
__device__ __forceinline__ void mma_bf16(float* d, const uint32_t* a, const uint32_t* b) {
    asm volatile(
        "mma.sync.aligned.m16n8k16.row.col.f32.bf16.bf16.f32 "
        "{%0,%1,%2,%3}, {%4,%5,%6,%7}, {%8,%9}, {%0,%1,%2,%3};"
        : "+f"(d[0]), "+f"(d[1]), "+f"(d[2]), "+f"(d[3])
        : "r"(a[0]), "r"(a[1]), "r"(a[2]), "r"(a[3]), "r"(b[0]), "r"(b[1]));
}
__device__ __forceinline__ float fsig(float x) { return 1.0f / (1.0f + __expf(-x)); }
__device__ __forceinline__ void split_bf16(float x, bf16& hi, bf16& lo) {
    hi = __float2bfloat16(x);
    lo = __float2bfloat16(x - __bfloat162float(hi));
}

// ---------------- prep kernels ----------------
__global__ void sort_rows(const int* __restrict__ seqlen,
                          int* __restrict__ perm, int* __restrict__ slen,
                          int* __restrict__ nact) {
    __shared__ int keys[B_ROWS];
    const int i = threadIdx.x;
    keys[i] = seqlen[i];
    __syncthreads();
    const int k = keys[i];
    int rank = 0;
    for (int j = 0; j < B_ROWS; ++j) {
        int kj = keys[j];
        rank += (kj > k) || (kj == k && j < i);
    }
    perm[rank] = i;
    slen[rank] = k;
    if (i < T_STEPS) {
        int cnt = 0;
        for (int j = 0; j < B_ROWS; ++j) cnt += (keys[j] >= i + 1);
        nact[i] = cnt;
    }
}

__global__ void split_chars_tiled(const float* __restrict__ x,
                                  const int* __restrict__ perm,
                                  char* __restrict__ xt) {
    const int n = B_ROWS * T_STEPS * DIM_IN;
    int i = blockIdx.x * blockDim.x + threadIdx.x;
    if (i >= n) return;
    const int row_elems = T_STEPS * DIM_IN;
    int bs = i / row_elems, d = i - bs * row_elems;
    int t = d >> 8, k = d & 255;
    float v = x[(size_t)perm[bs] * row_elems + d];
    bf16 h, l; split_bf16(v, h, l);
    size_t base = (((size_t)t * 8 + (bs >> 6)) * 8 + (k >> 5)) * A_TILE_B
                + (size_t)(bs & 63) * 80 + (k & 31) * 2;
    *reinterpret_cast<bf16*>(xt + base)             = h;
    *reinterpret_cast<bf16*>(xt + base + A_PLANE_B) = l;
}

struct TransArgs { const float* W; char* Wt; int K; };
__global__ void transpose_split_w_all(TransArgs t0, TransArgs t1,
                                      TransArgs t2, TransArgs t3) {
    TransArgs ta = (blockIdx.z == 0) ? t0
                 : (blockIdx.z == 1) ? t1
                 : (blockIdx.z == 2) ? t2 : t3;
    int kb = blockIdx.y * 32;
    if (kb >= ta.K) return;
    __shared__ float tile[32][33];
    int nb = blockIdx.x * 32;
    int x = threadIdx.x, y = threadIdx.y;
    #pragma unroll
    for (int yy = y; yy < 32; yy += 8)
        tile[yy][x] = ta.W[(size_t)(kb + yy) * FOURH + nb + x];
    __syncthreads();
    const int KC = ta.K >> 5;
    #pragma unroll
    for (int yy = y; yy < 32; yy += 8) {
        float w = tile[x][yy];
        bf16 h, l; split_bf16(w, h, l);
        int n4 = nb + yy, k = kb + x;
        int g = n4 >> 10, rr = n4 & 1023;
        int nblk = rr >> 5, nl = rr & 31;
        int kc = k >> 5, kl = k & 31;
        size_t base = ((size_t)(nblk * KC + kc)) * B_TILE_B
                    + (size_t)(g * 32 + nl) * 80 + kl * 2;
        *reinterpret_cast<bf16*>(ta.Wt + base)             = h;
        *reinterpret_cast<bf16*>(ta.Wt + base + B_PLANE_B) = l;
    }
}

// ---------------- per-layer step arguments ----------------
struct StepArgs {
    const char* Ax;
    const char* Hx;
    const char* Bw;
    const char* Bu;
    int KC0;
    const float* bias;
    float* C;
    char* Ot;
    const int* seqlen;
    float* hfinal;
    const int* nact;
    int t; int first;
};

// ------- fused dual-layer LSTM step: warp-specialized, x4-B-loads -------
__global__ __launch_bounds__(NTH)
void lstm_step(const StepArgs a0, const StepArgs a1)
{
    const StepArgs a = (blockIdx.z == 0) ? a0 : a1;
    const int rowblk = blockIdx.y;
    const int row0 = rowblk * BM;
    if (row0 >= a.nact[a.t]) return;

    extern __shared__ char smemc[];
    const uint32_t sb = smem_u32(smemc);
    const int tid  = threadIdx.x;
    const int lane = tid & 31;
    const int warp = tid >> 5;
    const int nblk = blockIdx.x;
    const int n0   = nblk * BN;

    const int KC0i = a.KC0;
    const int nch = a.first ? KC0i : (KC0i + 32);

    if (tid == 0) {
        #pragma unroll
        for (int s = 0; s < 3; ++s) {
            mbar_init(sb + SM_FULL(s), 1);
            mbar_init(sb + SM_EMPTY(s), 8);
        }
        asm volatile("fence.proxy.async.shared::cta;" ::: "memory");
    }
    __syncthreads();

    if (warp == 8) {
        // ---------------- producer warp ----------------
        if (lane == 0) {
            for (int c = 0; c < nch; ++c) {
                const int st = c % 3;
                if (c >= 3)
                    mbar_wait(sb + SM_EMPTY(st), (uint32_t)(((c / 3) - 1) & 1));
                const int seg = (c < KC0i) ? 0 : 1;
                const int kc  = seg ? (c - KC0i) : c;
                const char* As = seg ? (a.Hx + ((size_t)(rowblk * 32 + kc)) * A_TILE_B)
                                     : (a.Ax + ((size_t)(rowblk * KC0i + kc)) * A_TILE_B);
                const char* Bs = seg ? (a.Bu + ((size_t)(nblk * 32 + kc)) * B_TILE_B)
                                     : (a.Bw + ((size_t)(nblk * KC0i + kc)) * B_TILE_B);
                const uint32_t mb = sb + SM_FULL(st);
                mbar_expect(mb, STAGE_B);
                bulk_g2s(sb + SM_A_OFF(st), As, A_TILE_B, mb);
                bulk_g2s(sb + SM_B_OFF(st), Bs, B_TILE_B, mb);
            }
        }
        return;
    }

    // ---------------- consumer warps (0..7) ----------------
    const int wm = warp >> 1;            // 0..3 -> 16-row slab
    const int wn = warp & 1;             // 0..1 -> 16-col slab

    // A x4 lane mapping (16 rows x 2 k-halves)
    const int arow  = (lane & 7) + ((lane >> 3) & 1) * 8;
    const int koffA = (lane >> 4) * 8;
    // B x4 lane mapping: tiles = (nt0,k0),(nt0,k8),(nt1,k0),(nt1,k8)
    const int brow4 = (lane & 7) + ((lane >> 4) << 3);
    const int koffB4 = ((lane >> 3) & 1) * 8;

    float acc[4][2][4];
    #pragma unroll
    for (int g = 0; g < 4; ++g)
        #pragma unroll
        for (int nt = 0; nt < 2; ++nt)
            #pragma unroll
            for (int q = 0; q < 4; ++q) acc[g][nt][q] = 0.f;

    for (int i = 0; i < nch; ++i) {
        const int st = i % 3;
        mbar_wait(sb + SM_FULL(st), (uint32_t)((i / 3) & 1));

        const uint32_t aB = sb + SM_A_OFF(st);
        const uint32_t bB = sb + SM_B_OFF(st);

        #pragma unroll
        for (int ks = 0; ks < 2; ++ks) {
            uint32_t ah[4], al[4];
            uint32_t aa = aB + (uint32_t)((wm * 16 + arow) * 80 + (ks * 16 + koffA) * 2);
            ldmx4(ah, aa);
            ldmx4(al, aa + A_PLANE_B);
            #pragma unroll
            for (int g = 0; g < 4; ++g) {
                uint32_t bh[4], bl[4];
                uint32_t ba = bB + (uint32_t)((g * 32 + wn * 16 + brow4) * 80
                                              + (ks * 16 + koffB4) * 2);
                ldmx4(bh, ba);
                ldmx4(bl, ba + B_PLANE_B);
                // nt = 0 : registers {bh[0],bh[1]} / {bl[0],bl[1]}
                mma_bf16(acc[g][0], ah, bh);
                mma_bf16(acc[g][0], ah, bl);
                mma_bf16(acc[g][0], al, bh);
                // nt = 1 : registers {bh[2],bh[3]} / {bl[2],bl[3]}
                mma_bf16(acc[g][1], ah, bh + 2);
                mma_bf16(acc[g][1], ah, bl + 2);
                mma_bf16(acc[g][1], al, bh + 2);
            }
        }
        __syncwarp();
        if (lane == 0) mbar_arrive(sb + SM_EMPTY(st));
    }

    // ---- fused LSTM cell epilogue (h written in tiled A-image layout) ----
    #pragma unroll
    for (int half = 0; half < 2; ++half) {
        const int r = row0 + wm * 16 + half * 8 + (lane >> 2);
        const int slen = a.seqlen ? a.seqlen[r] : 0;
        #pragma unroll
        for (int nt = 0; nt < 2; ++nt) {
            const int c = n0 + wn * 16 + nt * 8 + (lane & 3) * 2;
            float2 cold = make_float2(0.f, 0.f);
            if (!a.first)
                cold = *reinterpret_cast<const float2*>(a.C + (size_t)r * HDIM + c);
            float cn[2], hn[2];
            #pragma unroll
            for (int j = 0; j < 2; ++j) {
                const int q = half * 2 + j;
                float zi = acc[0][nt][q] + a.bias[c + j];
                float zf = acc[1][nt][q] + a.bias[HDIM + c + j];
                float zg = acc[2][nt][q] + a.bias[2 * HDIM + c + j];
                float zo = acc[3][nt][q] + a.bias[3 * HDIM + c + j];
                float ig = fsig(zi), fg = fsig(zf);
                float gg = tanhf(zg), og = fsig(zo);
                float co = (j == 0) ? cold.x : cold.y;
                cn[j] = fmaf(fg, co, ig * gg);
                hn[j] = og * tanhf(cn[j]);
            }
            *reinterpret_cast<float2*>(a.C + (size_t)r * HDIM + c) = make_float2(cn[0], cn[1]);
            bf16 h0, l0, h1, l1;
            split_bf16(hn[0], h0, l0);
            split_bf16(hn[1], h1, l1);
            size_t toff = ((size_t)((r >> 6) * 32 + (c >> 5))) * A_TILE_B
                        + (size_t)(r & 63) * 80 + (c & 31) * 2;
            *reinterpret_cast<__nv_bfloat162*>(a.Ot + toff) = __nv_bfloat162(h0, h1);
            *reinterpret_cast<__nv_bfloat162*>(a.Ot + toff + A_PLANE_B) =
                __nv_bfloat162(l0, l1);
            if (a.hfinal && slen - 1 == a.t)
                *reinterpret_cast<float2*>(a.hfinal + (size_t)r * HDIM + c) =
                    make_float2(hn[0], hn[1]);
        }
    }
}

// ---------------- final dense(1024->3) + relu (sorted -> original order) ----------------
__global__ void dense_kernel(const float* __restrict__ hfinal,
                             const int* __restrict__ perm,
                             const float* __restrict__ Wd,
                             const float* __restrict__ bd,
                             float* __restrict__ out)
{
    const int bs = blockIdx.x;
    const float* h = hfinal + (size_t)bs * HDIM;

    float s0 = 0.f, s1 = 0.f, s2 = 0.f;
    for (int k = threadIdx.x; k < HDIM; k += blockDim.x) {
        float hv = h[k];
        s0 = fmaf(hv, Wd[k * 3 + 0], s0);
        s1 = fmaf(hv, Wd[k * 3 + 1], s1);
        s2 = fmaf(hv, Wd[k * 3 + 2], s2);
    }
    #pragma unroll
    for (int o = 16; o > 0; o >>= 1) {
        s0 += __shfl_down_sync(0xffffffffu, s0, o);
        s1 += __shfl_down_sync(0xffffffffu, s1, o);
        s2 += __shfl_down_sync(0xffffffffu, s2, o);
    }
    __shared__ float red[8][3];
    const int wid = threadIdx.x >> 5, lane = threadIdx.x & 31;
    if (lane == 0) { red[wid][0] = s0; red[wid][1] = s1; red[wid][2] = s2; }
    __syncthreads();
    if (threadIdx.x == 0) {
        float r0 = 0.f, r1 = 0.f, r2 = 0.f;
        const int nw = blockDim.x >> 5;
        for (int w = 0; w < nw; ++w) { r0 += red[w][0]; r1 += red[w][1]; r2 += red[w][2]; }
        const int b = perm[bs];
        out[b * 3 + 0] = fmaxf(r0 + bd[0], 0.f);
        out[b * 3 + 1] = fmaxf(r1 + bd[1], 0.f);
        out[b * 3 + 2] = fmaxf(r2 + bd[2], 0.f);
    }
}

extern "C" void kernel_launch(void* const* d_in, const int* in_sizes, int n_in,
                              void* d_out, int out_size) {
    const float* chars  = (const float*)d_in[0];
    const int*   seqlen = (const int*)  d_in[1];
    const float* W1 = (const float*)d_in[2];
    const float* U1 = (const float*)d_in[3];
    const float* b1 = (const float*)d_in[4];
    const float* W2 = (const float*)d_in[5];
    const float* U2 = (const float*)d_in[6];
    const float* b2 = (const float*)d_in[7];
    const float* Wd = (const float*)d_in[8];
    const float* bd = (const float*)d_in[9];
    float* out = (float*)d_out;

    char *xt, *h1t, *h2t, *w1t, *u1t, *w2t, *u2t;
    float *c1, *c2, *hfin;
    int *perm, *slen, *nact;
    cudaGetSymbolAddress((void**)&xt,   g_xt);
    cudaGetSymbolAddress((void**)&h1t,  g_h1t);
    cudaGetSymbolAddress((void**)&h2t,  g_h2t);
    cudaGetSymbolAddress((void**)&w1t,  g_w1t);
    cudaGetSymbolAddress((void**)&u1t,  g_u1t);
    cudaGetSymbolAddress((void**)&w2t,  g_w2t);
    cudaGetSymbolAddress((void**)&u2t,  g_u2t);
    cudaGetSymbolAddress((void**)&c1,   g_c1);
    cudaGetSymbolAddress((void**)&c2,   g_c2);
    cudaGetSymbolAddress((void**)&hfin, g_hfinal);
    cudaGetSymbolAddress((void**)&perm, g_perm);
    cudaGetSymbolAddress((void**)&slen, g_slen);
    cudaGetSymbolAddress((void**)&nact, g_nact);

    cudaFuncSetAttribute(lstm_step,
                         cudaFuncAttributeMaxDynamicSharedMemorySize, SMEM_BYTES);

    const size_t HSLOT = (size_t)8 * 32 * A_TILE_B;

    // prep (3 launches so ncu -s 5 lands on lstm_step)
    sort_rows<<<1, B_ROWS>>>(seqlen, perm, slen, nact);
    const int nx = B_ROWS * T_STEPS * DIM_IN;
    split_chars_tiled<<<(nx + 255) / 256, 256>>>(chars, perm, xt);
    {
        TransArgs t0 = {W1, w1t, DIM_IN};
        TransArgs t1 = {U1, u1t, HDIM};
        TransArgs t2 = {W2, w2t, HDIM};
        TransArgs t3 = {U2, u2t, HDIM};
        transpose_split_w_all<<<dim3(FOURH / 32, HDIM / 32, 4), dim3(32, 8)>>>(t0, t1, t2, t3);
    }

    auto mkL1 = [&](int t) {
        StepArgs s;
        const int prev = t & 1, cur = (t + 1) & 1;
        s.Ax = xt + (size_t)t * 8 * 8 * A_TILE_B;
        s.Hx = h1t + prev * HSLOT;
        s.Bw = w1t; s.Bu = u1t;
        s.KC0 = DIM_IN / 32;
        s.bias = b1; s.C = c1;
        s.Ot = h1t + cur * HSLOT;
        s.seqlen = nullptr; s.hfinal = nullptr;
        s.nact = nact;
        s.t = t; s.first = (t == 0) ? 1 : 0;
        return s;
    };
    auto mkL2 = [&](int t) {
        StepArgs s;
        const int prev = t & 1, cur = (t + 1) & 1;
        s.Ax = h1t + cur * HSLOT;
        s.Hx = h2t + prev * HSLOT;
        s.Bw = w2t; s.Bu = u2t;
        s.KC0 = HDIM / 32;
        s.bias = b2; s.C = c2;
        s.Ot = h2t + cur * HSLOT;
        s.seqlen = slen; s.hfinal = hfin;
        s.nact = nact;
        s.t = t; s.first = (t == 0) ? 1 : 0;
        return s;
    };

    const dim3 grid1(HDIM / BN, B_ROWS / BM, 1);   // (32, 8, 1)
    const dim3 grid2(HDIM / BN, B_ROWS / BM, 2);   // (32, 8, 2)

    {
        StepArgs s = mkL1(0);
        lstm_step<<<grid1, NTH, SMEM_BYTES>>>(s, s);
    }
    for (int k = 1; k < T_STEPS; ++k) {
        StepArgs sA = mkL1(k);
        StepArgs sB = mkL2(k - 1);
        lstm_step<<<grid2, NTH, SMEM_BYTES>>>(sA, sB);
    }
    {
        StepArgs s = mkL2(T_STEPS - 1);
        lstm_step<<<grid1, NTH, SMEM_BYTES>>>(s, s);
    }
    dense_kernel<<<B_ROWS, 256>>>(hfin, perm, Wd, bd, out);
}